// round 1
// baseline (speedup 1.0000x reference)
#include <cuda_runtime.h>
#include <cstdint>

#define NE 32
#define TOPK 4
#define HDIM 1024
#define IDIM 1024
#define NT 2048
#define N2I 2048
#define ALPHA 1.702f
#define LIMIT 7.0f

// ---------------- device scratch (static globals; no allocation) ----------------
__device__ int   g_cnt[NE];
__device__ int   g_off[NE];
__device__ int   g_list[NE * NT];
__device__ float g_wgt[NE * NT];
__device__ float g_act[(size_t)TOPK * NT * IDIM];   // 8192 x 1024 fp32 = 32 MB

// ---------------- helpers ----------------
__device__ __forceinline__ uint32_t f2tf(float f) {
    uint32_t u;
    asm("cvt.rna.tf32.f32 %0, %1;" : "=r"(u) : "f"(f));
    return u;
}

__device__ __forceinline__ void mma_tf32(float* c, const uint32_t* a, const uint32_t* b) {
    asm volatile(
        "mma.sync.aligned.m16n8k8.row.col.f32.tf32.tf32.f32 "
        "{%0,%1,%2,%3}, {%4,%5,%6,%7}, {%8,%9}, {%0,%1,%2,%3};"
        : "+f"(c[0]), "+f"(c[1]), "+f"(c[2]), "+f"(c[3])
        : "r"(a[0]), "r"(a[1]), "r"(a[2]), "r"(a[3]), "r"(b[0]), "r"(b[1]));
}

// ---------------- kernel 0: zero output + counters ----------------
__global__ void zero_kernel(float* __restrict__ routed) {
    int i = blockIdx.x * blockDim.x + threadIdx.x;
    if (i < NT * HDIM) routed[i] = 0.0f;
    if (blockIdx.x == 0 && threadIdx.x < NE) g_cnt[threadIdx.x] = 0;
}

// ---------------- kernel 1: router (fp32, exact) ----------------
__global__ void router_kernel(const float* __restrict__ x,
                              const float* __restrict__ rw,
                              const float* __restrict__ rb,
                              float* __restrict__ scores) {
    int t = blockIdx.x;
    __shared__ float sx[HDIM];
    __shared__ float slog[NE];
    __shared__ int   sidx[TOPK];
    __shared__ float swt[TOPK];

    int tid = threadIdx.x;
    for (int i = tid; i < HDIM; i += 128) sx[i] = x[(size_t)t * HDIM + i];
    __syncthreads();

    int w = tid >> 5, lane = tid & 31;
    for (int j = 0; j < 8; j++) {
        int e = w * 8 + j;
        const float* wr = rw + (size_t)e * HDIM;
        float acc = 0.0f;
        for (int h = lane; h < HDIM; h += 32) acc += sx[h] * wr[h];
        #pragma unroll
        for (int s = 16; s > 0; s >>= 1) acc += __shfl_down_sync(0xffffffffu, acc, s);
        if (lane == 0) slog[e] = acc + rb[e];
    }
    __syncthreads();

    if (tid == 0) {
        bool used[NE];
        #pragma unroll
        for (int e = 0; e < NE; e++) used[e] = false;
        for (int k = 0; k < TOPK; k++) {
            float best = -1e30f; int bi = 0;
            for (int e = 0; e < NE; e++) {
                if (!used[e] && slog[e] > best) { best = slog[e]; bi = e; }
            }
            used[bi] = true; sidx[k] = bi; swt[k] = best;
        }
        float m = swt[0];
        float s = 0.0f;
        for (int k = 0; k < TOPK; k++) { swt[k] = expf(swt[k] - m); s += swt[k]; }
        float inv = 1.0f / s;
        for (int k = 0; k < TOPK; k++) {
            swt[k] *= inv;
            int e = sidx[k];
            int pos = atomicAdd(&g_cnt[e], 1);
            g_list[e * NT + pos] = t;
            g_wgt[e * NT + pos]  = swt[k];
        }
    }
    __syncthreads();

    if (tid < NE) {
        float v = 0.0f;
        #pragma unroll
        for (int k = 0; k < TOPK; k++)
            if (sidx[k] == tid) v = swt[k];
        scores[(size_t)t * NE + tid] = v;
    }
}

// ---------------- kernel 2: exclusive scan of expert counts ----------------
__global__ void scan_kernel() {
    if (threadIdx.x == 0) {
        int s = 0;
        for (int e = 0; e < NE; e++) { g_off[e] = s; s += g_cnt[e]; }
    }
}

// ---------------- kernel 3: gate_up GEMM + activation -> g_act ----------------
// BM=64 tokens, BN=128 gate_up cols (=64 act cols), BK=32, 256 threads
__global__ __launch_bounds__(256) void gateup_kernel(
    const float* __restrict__ x,
    const float* __restrict__ gup,
    const float* __restrict__ gub) {

    int e = blockIdx.z, mt = blockIdx.y, nt = blockIdx.x;
    int cnt = g_cnt[e];
    if (mt * 64 >= cnt) return;
    int off = g_off[e];

    __shared__ float sA[64][36];
    __shared__ float sB[32][132];
    __shared__ int   sTok[64];

    int tid = threadIdx.x;
    if (tid < 64) {
        int r = mt * 64 + tid;
        sTok[tid] = (r < cnt) ? g_list[e * NT + r] : 0;
    }
    __syncthreads();

    int warp = tid >> 5, lane = tid & 31;
    int wm = warp & 1, wn = warp >> 1;   // warps: 2 (M) x 4 (N), warp tile 32x32
    int r0 = lane >> 2, c0 = lane & 3;

    float acc[2][4][4];
    #pragma unroll
    for (int mi = 0; mi < 2; mi++)
        #pragma unroll
        for (int ni = 0; ni < 4; ni++)
            #pragma unroll
            for (int q = 0; q < 4; q++) acc[mi][ni][q] = 0.0f;

    int la_row = tid >> 2;          // 0..63
    int la_col = (tid & 3) * 8;     // 0,8,16,24
    int lb_row = tid >> 3;          // 0..31
    int lb_col = (tid & 7) * 16;    // 0..112

    const float* Bbase = gup + (size_t)e * HDIM * N2I + nt * 128;
    const float* Arow  = x + (size_t)sTok[la_row] * HDIM;

    for (int k0 = 0; k0 < HDIM; k0 += 32) {
        // load A tile (gathered token rows)
        const float* ax = Arow + k0 + la_col;
        float4 v0 = *(const float4*)(ax);
        float4 v1 = *(const float4*)(ax + 4);
        *(float4*)&sA[la_row][la_col]     = v0;
        *(float4*)&sA[la_row][la_col + 4] = v1;
        // load B tile
        const float* bx = Bbase + (size_t)(k0 + lb_row) * N2I + lb_col;
        #pragma unroll
        for (int q = 0; q < 4; q++)
            *(float4*)&sB[lb_row][lb_col + q * 4] = *(const float4*)(bx + q * 4);
        __syncthreads();

        #pragma unroll
        for (int kk = 0; kk < 4; kk++) {
            int kb = kk * 8;
            uint32_t a[2][4], b[4][2];
            #pragma unroll
            for (int mi = 0; mi < 2; mi++) {
                int rbase = wm * 32 + mi * 16;
                a[mi][0] = f2tf(sA[rbase + r0][kb + c0]);
                a[mi][1] = f2tf(sA[rbase + r0 + 8][kb + c0]);
                a[mi][2] = f2tf(sA[rbase + r0][kb + c0 + 4]);
                a[mi][3] = f2tf(sA[rbase + r0 + 8][kb + c0 + 4]);
            }
            #pragma unroll
            for (int ni = 0; ni < 4; ni++) {
                int ncol = wn * 32 + ni * 8 + r0;
                b[ni][0] = f2tf(sB[kb + c0][ncol]);
                b[ni][1] = f2tf(sB[kb + c0 + 4][ncol]);
            }
            #pragma unroll
            for (int mi = 0; mi < 2; mi++)
                #pragma unroll
                for (int ni = 0; ni < 4; ni++)
                    mma_tf32(acc[mi][ni], a[mi], b[ni]);
        }
        __syncthreads();
    }

    // epilogue: bias + clamp + glu, write act
    const float* gubp = gub + (size_t)e * N2I;
    #pragma unroll
    for (int mi = 0; mi < 2; mi++) {
        #pragma unroll
        for (int ni = 0; ni < 4; ni++) {
            int rl = mt * 64 + wm * 32 + mi * 16 + r0;
            int gn = nt * 128 + wn * 32 + ni * 8 + c0 * 2;
            #pragma unroll
            for (int half = 0; half < 2; half++) {
                int rr = rl + half * 8;
                if (rr < cnt) {
                    float gate = acc[mi][ni][half * 2 + 0] + gubp[gn];
                    float up   = acc[mi][ni][half * 2 + 1] + gubp[gn + 1];
                    gate = fminf(gate, LIMIT);
                    up   = fminf(fmaxf(up, -LIMIT), LIMIT);
                    float glu = gate * (1.0f / (1.0f + __expf(-ALPHA * gate)));
                    g_act[(size_t)(off + rr) * IDIM + (gn >> 1)] = (up + 1.0f) * glu;
                }
            }
        }
    }
}

// ---------------- kernel 4: down GEMM + weighted scatter-add ----------------
// BM=64 rows, BN=64 H-cols, BK=32, 256 threads
__global__ __launch_bounds__(256) void down_kernel(
    const float* __restrict__ dw,
    const float* __restrict__ db,
    float* __restrict__ outp) {

    int e = blockIdx.z, mt = blockIdx.y, nt = blockIdx.x;
    int cnt = g_cnt[e];
    if (mt * 64 >= cnt) return;
    int off = g_off[e];

    __shared__ float sA[64][36];
    __shared__ float sB[32][68];
    __shared__ int   sTok[64];
    __shared__ float sW[64];

    int tid = threadIdx.x;
    if (tid < 64) {
        int r = mt * 64 + tid;
        bool v = r < cnt;
        sTok[tid] = v ? g_list[e * NT + r] : 0;
        sW[tid]   = v ? g_wgt[e * NT + r]  : 0.0f;
    }
    __syncthreads();

    int warp = tid >> 5, lane = tid & 31;
    int wm = warp & 1, wn = warp >> 1;   // 2 (M) x 4 (N), warp tile 32x16
    int r0 = lane >> 2, c0 = lane & 3;

    float acc[2][2][4];
    #pragma unroll
    for (int mi = 0; mi < 2; mi++)
        #pragma unroll
        for (int ni = 0; ni < 2; ni++)
            #pragma unroll
            for (int q = 0; q < 4; q++) acc[mi][ni][q] = 0.0f;

    int la_row = tid >> 2;        // 0..63
    int la_col = (tid & 3) * 8;
    int lb_row = tid >> 3;        // 0..31
    int lb_col = (tid & 7) * 8;

    bool a_valid = (mt * 64 + la_row) < cnt;
    const float* Abase = g_act + (size_t)(off + mt * 64 + la_row) * IDIM;
    const float* Bbase = dw + (size_t)e * IDIM * HDIM + nt * 64;

    for (int k0 = 0; k0 < IDIM; k0 += 32) {
        float4 v0 = make_float4(0.f, 0.f, 0.f, 0.f), v1 = v0;
        if (a_valid) {
            const float* ax = Abase + k0 + la_col;
            v0 = *(const float4*)(ax);
            v1 = *(const float4*)(ax + 4);
        }
        *(float4*)&sA[la_row][la_col]     = v0;
        *(float4*)&sA[la_row][la_col + 4] = v1;

        const float* bx = Bbase + (size_t)(k0 + lb_row) * HDIM + lb_col;
        *(float4*)&sB[lb_row][lb_col]     = *(const float4*)(bx);
        *(float4*)&sB[lb_row][lb_col + 4] = *(const float4*)(bx + 4);
        __syncthreads();

        #pragma unroll
        for (int kk = 0; kk < 4; kk++) {
            int kb = kk * 8;
            uint32_t a[2][4], b[2][2];
            #pragma unroll
            for (int mi = 0; mi < 2; mi++) {
                int rbase = wm * 32 + mi * 16;
                a[mi][0] = f2tf(sA[rbase + r0][kb + c0]);
                a[mi][1] = f2tf(sA[rbase + r0 + 8][kb + c0]);
                a[mi][2] = f2tf(sA[rbase + r0][kb + c0 + 4]);
                a[mi][3] = f2tf(sA[rbase + r0 + 8][kb + c0 + 4]);
            }
            #pragma unroll
            for (int ni = 0; ni < 2; ni++) {
                int ncol = wn * 16 + ni * 8 + r0;
                b[ni][0] = f2tf(sB[kb + c0][ncol]);
                b[ni][1] = f2tf(sB[kb + c0 + 4][ncol]);
            }
            #pragma unroll
            for (int mi = 0; mi < 2; mi++)
                #pragma unroll
                for (int ni = 0; ni < 2; ni++)
                    mma_tf32(acc[mi][ni], a[mi], b[ni]);
        }
        __syncthreads();
    }

    const float* dbp = db + (size_t)e * HDIM;
    #pragma unroll
    for (int mi = 0; mi < 2; mi++) {
        #pragma unroll
        for (int ni = 0; ni < 2; ni++) {
            int rl = mt * 64 + wm * 32 + mi * 16 + r0;
            int gn = nt * 64 + wn * 16 + ni * 8 + c0 * 2;
            #pragma unroll
            for (int half = 0; half < 2; half++) {
                int rr = rl + half * 8;
                if (rr < cnt) {
                    int li  = rr - mt * 64;
                    int tok = sTok[li];
                    float w = sW[li];
                    float d0 = (acc[mi][ni][half * 2 + 0] + dbp[gn]) * w;
                    float d1 = (acc[mi][ni][half * 2 + 1] + dbp[gn + 1]) * w;
                    atomicAdd(&outp[(size_t)tok * HDIM + gn],     d0);
                    atomicAdd(&outp[(size_t)tok * HDIM + gn + 1], d1);
                }
            }
        }
    }
}

// ---------------- launch ----------------
extern "C" void kernel_launch(void* const* d_in, const int* in_sizes, int n_in,
                              void* d_out, int out_size) {
    const float* x   = (const float*)d_in[0];
    const float* gup = (const float*)d_in[1];
    const float* gub = (const float*)d_in[2];
    const float* dw  = (const float*)d_in[3];
    const float* db  = (const float*)d_in[4];
    const float* rw  = (const float*)d_in[5];
    const float* rb  = (const float*)d_in[6];

    float* routed = (float*)d_out;
    float* scores = (float*)d_out + (out_size - NT * NE);

    zero_kernel<<<(NT * HDIM + 1023) / 1024, 1024>>>(routed);
    router_kernel<<<NT, 128>>>(x, rw, rb, scores);
    scan_kernel<<<1, 32>>>();
    gateup_kernel<<<dim3(16, 32, 32), 256>>>(x, gup, gub);
    down_kernel<<<dim3(16, 32, 32), 256>>>(dw, db, routed);
}

// round 4
// speedup vs baseline: 1.2683x; 1.2683x over previous
#include <cuda_runtime.h>
#include <cstdint>

#define NE 32
#define TOPK 4
#define HDIM 1024
#define IDIM 1024
#define NT 2048
#define N2I 2048
#define ALPHA 1.702f
#define LIMIT 7.0f

// ---------------- device scratch ----------------
__device__ int   g_cnt[NE];
__device__ int   g_off[NE];
__device__ int   g_list[NE * NT];
__device__ float g_wgt[NE * NT];
__device__ float g_act[(size_t)TOPK * NT * IDIM];   // 8192 x 1024, pre-rounded tf32

// ---------------- helpers ----------------
__device__ __forceinline__ uint32_t f2tf(float f) {
    uint32_t u;
    asm("cvt.rna.tf32.f32 %0, %1;" : "=r"(u) : "f"(f));
    return u;
}

__device__ __forceinline__ void mma_tf32(float* c, const uint32_t* a, const uint32_t* b) {
    asm volatile(
        "mma.sync.aligned.m16n8k8.row.col.f32.tf32.tf32.f32 "
        "{%0,%1,%2,%3}, {%4,%5,%6,%7}, {%8,%9}, {%0,%1,%2,%3};"
        : "+f"(c[0]), "+f"(c[1]), "+f"(c[2]), "+f"(c[3])
        : "r"(a[0]), "r"(a[1]), "r"(a[2]), "r"(a[3]), "r"(b[0]), "r"(b[1]));
}

__device__ __forceinline__ void cp16a(uint32_t dst, const void* src, int sz) {
    asm volatile("cp.async.ca.shared.global [%0], [%1], 16, %2;"
                 :: "r"(dst), "l"(src), "r"(sz));
}
__device__ __forceinline__ void cp16b(uint32_t dst, const void* src) {
    asm volatile("cp.async.cg.shared.global [%0], [%1], 16;"
                 :: "r"(dst), "l"(src));
}
#define CP_COMMIT asm volatile("cp.async.commit_group;")
#define CP_WAIT1  asm volatile("cp.async.wait_group 1;" ::: "memory")
#define CP_WAIT0  asm volatile("cp.async.wait_group 0;" ::: "memory")

// ---------------- kernel 0: zero output + counters ----------------
__global__ void zero_kernel(float* __restrict__ routed) {
    int i = blockIdx.x * blockDim.x + threadIdx.x;
    if (i < NT * HDIM) routed[i] = 0.0f;
    if (blockIdx.x == 0 && threadIdx.x < NE) g_cnt[threadIdx.x] = 0;
}

// ---------------- kernel 1: router ----------------
__global__ void router_kernel(const float* __restrict__ x,
                              const float* __restrict__ rw,
                              const float* __restrict__ rb,
                              float* __restrict__ scores) {
    int t = blockIdx.x;
    __shared__ float sx[HDIM];
    __shared__ float slog[NE];
    __shared__ int   sidx[TOPK];
    __shared__ float swt[TOPK];

    int tid = threadIdx.x;
    for (int i = tid; i < HDIM; i += 128) sx[i] = x[(size_t)t * HDIM + i];
    __syncthreads();

    int w = tid >> 5, lane = tid & 31;
    for (int j = 0; j < 8; j++) {
        int e = w * 8 + j;
        const float* wr = rw + (size_t)e * HDIM;
        float acc = 0.0f;
        for (int h = lane; h < HDIM; h += 32) acc += sx[h] * wr[h];
        #pragma unroll
        for (int s = 16; s > 0; s >>= 1) acc += __shfl_down_sync(0xffffffffu, acc, s);
        if (lane == 0) slog[e] = acc + rb[e];
    }
    __syncthreads();

    if (tid == 0) {
        bool used[NE];
        #pragma unroll
        for (int e = 0; e < NE; e++) used[e] = false;
        for (int k = 0; k < TOPK; k++) {
            float best = -1e30f; int bi = 0;
            for (int e = 0; e < NE; e++)
                if (!used[e] && slog[e] > best) { best = slog[e]; bi = e; }
            used[bi] = true; sidx[k] = bi; swt[k] = best;
        }
        float m = swt[0];
        float s = 0.0f;
        for (int k = 0; k < TOPK; k++) { swt[k] = expf(swt[k] - m); s += swt[k]; }
        float inv = 1.0f / s;
        for (int k = 0; k < TOPK; k++) {
            swt[k] *= inv;
            int e = sidx[k];
            int pos = atomicAdd(&g_cnt[e], 1);
            g_list[e * NT + pos] = t;
            g_wgt[e * NT + pos]  = swt[k];
        }
    }
    __syncthreads();

    if (tid < NE) {
        float v = 0.0f;
        #pragma unroll
        for (int k = 0; k < TOPK; k++)
            if (sidx[k] == tid) v = swt[k];
        scores[(size_t)t * NE + tid] = v;
    }
}

// ---------------- kernel 2: exclusive scan ----------------
__global__ void scan_kernel() {
    if (threadIdx.x == 0) {
        int s = 0;
        for (int e = 0; e < NE; e++) { g_off[e] = s; s += g_cnt[e]; }
    }
}

// ---------------- kernel 3: gate_up GEMM + activation ----------------
// BM=128, BN=128, BK=16, 128 threads (4 warps, 2x2, warp tile 64x64)
__global__ __launch_bounds__(128) void gateup_kernel(
    const float* __restrict__ x,
    const float* __restrict__ gup,
    const float* __restrict__ gub) {

    int e = blockIdx.z, mt = blockIdx.y, nt = blockIdx.x;
    int cnt = g_cnt[e];
    if (mt * 128 >= cnt) return;
    int off = g_off[e];

    __shared__ float sA[2][128][20];
    __shared__ float sB[2][16][132];

    int tid = threadIdx.x;
    int r = mt * 128 + tid;
    int tok = (r < cnt) ? g_list[e * NT + r] : -1;
    int apred = (tok >= 0) ? 16 : 0;
    const float* aSrc = x + (size_t)(tok >= 0 ? tok : 0) * HDIM;
    const float* bSrc = gup + (size_t)e * HDIM * N2I + nt * 128;

    uint32_t aBase = (uint32_t)__cvta_generic_to_shared(&sA[0][0][0]) + tid * 80;
    uint32_t bBase = (uint32_t)__cvta_generic_to_shared(&sB[0][0][0]);
    const uint32_t A_STAGE = 128 * 20 * 4;
    const uint32_t B_STAGE = 16 * 132 * 4;

    auto issue = [&](int s, int k0) {
        uint32_t ad = aBase + s * A_STAGE;
        const float* as = aSrc + k0;
        #pragma unroll
        for (int j = 0; j < 4; j++) cp16a(ad + j * 16, as + j * 4, apred);
        #pragma unroll
        for (int j = 0; j < 4; j++) {
            int idx = tid + j * 128;
            int k = idx >> 5, c = (idx & 31) * 4;
            cp16b(bBase + s * B_STAGE + k * 528 + c * 4,
                  bSrc + (size_t)(k0 + k) * N2I + c);
        }
    };

    issue(0, 0);  CP_COMMIT;
    issue(1, 16); CP_COMMIT;

    int warp = tid >> 5, lane = tid & 31;
    int wm = warp & 1, wn = warp >> 1;
    int r0 = lane >> 2, c0 = lane & 3;

    float acc[4][8][4] = {};

    CP_WAIT1;
    __syncthreads();

    for (int kt = 0; kt < 64; kt++) {
        int s = kt & 1;
        #pragma unroll
        for (int kk = 0; kk < 2; kk++) {
            int kb = kk * 8;
            uint32_t a[4][4], b[8][2];
            #pragma unroll
            for (int mi = 0; mi < 4; mi++) {
                int rb = wm * 64 + mi * 16 + r0;
                a[mi][0] = f2tf(sA[s][rb][kb + c0]);
                a[mi][1] = f2tf(sA[s][rb + 8][kb + c0]);
                a[mi][2] = f2tf(sA[s][rb][kb + c0 + 4]);
                a[mi][3] = f2tf(sA[s][rb + 8][kb + c0 + 4]);
            }
            #pragma unroll
            for (int ni = 0; ni < 8; ni++) {
                int ncl = wn * 64 + ni * 8 + r0;
                b[ni][0] = f2tf(sB[s][kb + c0][ncl]);
                b[ni][1] = f2tf(sB[s][kb + c0 + 4][ncl]);
            }
            #pragma unroll
            for (int mi = 0; mi < 4; mi++)
                #pragma unroll
                for (int ni = 0; ni < 8; ni++)
                    mma_tf32(acc[mi][ni], a[mi], b[ni]);
        }
        if (kt == 63) break;
        __syncthreads();
        if (kt + 2 < 64) { issue(s, (kt + 2) * 16); CP_COMMIT; CP_WAIT1; }
        else             { CP_WAIT0; }
        __syncthreads();
    }

    // epilogue: bias + clamp + glu; store pre-rounded tf32 into g_act
    const float* gubp = gub + (size_t)e * N2I + nt * 128;
    #pragma unroll
    for (int mi = 0; mi < 4; mi++)
        #pragma unroll
        for (int ni = 0; ni < 8; ni++)
            #pragma unroll
            for (int half = 0; half < 2; half++) {
                int li = wm * 64 + mi * 16 + r0 + half * 8;
                int rr = mt * 128 + li;
                if (rr < cnt) {
                    int ln = wn * 64 + ni * 8 + c0 * 2;
                    float gate = acc[mi][ni][half * 2 + 0] + gubp[ln];
                    float up   = acc[mi][ni][half * 2 + 1] + gubp[ln + 1];
                    gate = fminf(gate, LIMIT);
                    up   = fminf(fmaxf(up, -LIMIT), LIMIT);
                    float glu = gate * (1.0f / (1.0f + __expf(-ALPHA * gate)));
                    float v = (up + 1.0f) * glu;
                    g_act[(size_t)(off + rr) * IDIM + nt * 64 + wn * 32 + ni * 4 + c0] =
                        __uint_as_float(f2tf(v));
                }
            }
}

// ---------------- kernel 4: down GEMM + weighted scatter-add ----------------
// BM=128, BN=128, BK=16, 128 threads (4 warps, 2x2, warp tile 64x64)
__global__ __launch_bounds__(128) void down_kernel(
    const float* __restrict__ dw,
    const float* __restrict__ db,
    float* __restrict__ outp) {

    int e = blockIdx.z, mt = blockIdx.y, nt = blockIdx.x;
    int cnt = g_cnt[e];
    if (mt * 128 >= cnt) return;
    int off = g_off[e];

    __shared__ float sA[2][128][20];
    __shared__ float sB[2][16][132];
    __shared__ int   sTok[128];
    __shared__ float sW[128];

    int tid = threadIdx.x;
    int r = mt * 128 + tid;
    bool valid = r < cnt;
    sTok[tid] = valid ? g_list[e * NT + r] : 0;
    sW[tid]   = valid ? g_wgt[e * NT + r]  : 0.0f;

    int apred = valid ? 16 : 0;
    const float* aSrc = g_act + (size_t)(off + (valid ? r : 0)) * IDIM;
    const float* bSrc = dw + (size_t)e * IDIM * HDIM + nt * 128;

    uint32_t aBase = (uint32_t)__cvta_generic_to_shared(&sA[0][0][0]) + tid * 80;
    uint32_t bBase = (uint32_t)__cvta_generic_to_shared(&sB[0][0][0]);
    const uint32_t A_STAGE = 128 * 20 * 4;
    const uint32_t B_STAGE = 16 * 132 * 4;

    auto issue = [&](int s, int k0) {
        uint32_t ad = aBase + s * A_STAGE;
        const float* as = aSrc + k0;
        #pragma unroll
        for (int j = 0; j < 4; j++) cp16a(ad + j * 16, as + j * 4, apred);
        #pragma unroll
        for (int j = 0; j < 4; j++) {
            int idx = tid + j * 128;
            int k = idx >> 5, c = (idx & 31) * 4;
            cp16b(bBase + s * B_STAGE + k * 528 + c * 4,
                  bSrc + (size_t)(k0 + k) * HDIM + c);
        }
    };

    issue(0, 0);  CP_COMMIT;
    issue(1, 16); CP_COMMIT;

    int warp = tid >> 5, lane = tid & 31;
    int wm = warp & 1, wn = warp >> 1;
    int r0 = lane >> 2, c0 = lane & 3;

    float acc[4][8][4] = {};

    CP_WAIT1;
    __syncthreads();

    for (int kt = 0; kt < 64; kt++) {
        int s = kt & 1;
        #pragma unroll
        for (int kk = 0; kk < 2; kk++) {
            int kb = kk * 8;
            uint32_t a[4][4], b[8][2];
            #pragma unroll
            for (int mi = 0; mi < 4; mi++) {
                int rb = wm * 64 + mi * 16 + r0;
                // g_act pre-rounded to tf32: raw bits valid, no cvt
                a[mi][0] = __float_as_uint(sA[s][rb][kb + c0]);
                a[mi][1] = __float_as_uint(sA[s][rb + 8][kb + c0]);
                a[mi][2] = __float_as_uint(sA[s][rb][kb + c0 + 4]);
                a[mi][3] = __float_as_uint(sA[s][rb + 8][kb + c0 + 4]);
            }
            #pragma unroll
            for (int ni = 0; ni < 8; ni++) {
                int ncl = wn * 64 + ni * 8 + r0;
                b[ni][0] = f2tf(sB[s][kb + c0][ncl]);
                b[ni][1] = f2tf(sB[s][kb + c0 + 4][ncl]);
            }
            #pragma unroll
            for (int mi = 0; mi < 4; mi++)
                #pragma unroll
                for (int ni = 0; ni < 8; ni++)
                    mma_tf32(acc[mi][ni], a[mi], b[ni]);
        }
        if (kt == 63) break;
        __syncthreads();
        if (kt + 2 < 64) { issue(s, (kt + 2) * 16); CP_COMMIT; CP_WAIT1; }
        else             { CP_WAIT0; }
        __syncthreads();
    }

    const float* dbp = db + (size_t)e * HDIM + nt * 128;
    #pragma unroll
    for (int mi = 0; mi < 4; mi++)
        #pragma unroll
        for (int ni = 0; ni < 8; ni++)
            #pragma unroll
            for (int half = 0; half < 2; half++) {
                int li = wm * 64 + mi * 16 + r0 + half * 8;
                int rr = mt * 128 + li;
                if (rr < cnt) {
                    int tok2 = sTok[li];
                    float w  = sW[li];
                    int ln = wn * 64 + ni * 8 + c0 * 2;
                    float d0 = (acc[mi][ni][half * 2 + 0] + dbp[ln])     * w;
                    float d1 = (acc[mi][ni][half * 2 + 1] + dbp[ln + 1]) * w;
                    float* p = &outp[(size_t)tok2 * HDIM + nt * 128 + ln];
                    atomicAdd(p,     d0);
                    atomicAdd(p + 1, d1);
                }
            }
}

// ---------------- launch ----------------
extern "C" void kernel_launch(void* const* d_in, const int* in_sizes, int n_in,
                              void* d_out, int out_size) {
    const float* x   = (const float*)d_in[0];
    const float* gup = (const float*)d_in[1];
    const float* gub = (const float*)d_in[2];
    const float* dw  = (const float*)d_in[3];
    const float* db  = (const float*)d_in[4];
    const float* rw  = (const float*)d_in[5];
    const float* rb  = (const float*)d_in[6];

    float* routed = (float*)d_out;
    float* scores = (float*)d_out + (out_size - NT * NE);

    zero_kernel<<<(NT * HDIM + 1023) / 1024, 1024>>>(routed);
    router_kernel<<<NT, 128>>>(x, rw, rb, scores);
    scan_kernel<<<1, 32>>>();
    gateup_kernel<<<dim3(16, 16, 32), 128>>>(x, gup, gub);
    down_kernel<<<dim3(8, 16, 32), 128>>>(dw, db, routed);
}